// round 15
// baseline (speedup 1.0000x reference)
#include <cuda_runtime.h>
#include <cuda_bf16.h>
#include <cstdint>

// N=100000 nodes, D=256 features, E=3200000 edges.
#define MAX_N 100000
#define FEAT_D 256
#define EDGE_ROLE_BLOCKS 444   // ~3 per SM: persistent atomic pumpers

__device__ float g_diag[MAX_N];   // sigmoid(x @ w + b)
__device__ float g_deg[MAX_N];    // degree over col (raw counts)

// ---------------------------------------------------------------------------
// is64 detection: int64 little-endian values < 2^32 have zero odd words.
// ---------------------------------------------------------------------------
__device__ __forceinline__ int detect_is64(const void* eidx) {
    const int* wds = reinterpret_cast<const int*>(eidx);
    int nz = 0;
    #pragma unroll
    for (int i = 0; i < 8; i++) nz |= wds[2 * i + 1];
    return nz == 0;
}

// ---------------------------------------------------------------------------
// Combined kernel, block-role split (R14 structure, slimmer edge role):
//   bid < EDGE_ROLE_BLOCKS : grid-stride, col-only degree atomics,
//                            8 edges/thread (2048-edge tiles) — L2-bound
//   else                   : one-shot diag tile of 16 rows    — DRAM-bound
// ---------------------------------------------------------------------------
__global__ void fused_deg_diag(const float* __restrict__ x,
                               const float* __restrict__ w,
                               const float* __restrict__ b,
                               const void* __restrict__ eidx,
                               int n, int E) {
    const int tid = threadIdx.x;

    if (blockIdx.x < EDGE_ROLE_BLOCKS) {
        // ---------------- edge role: col-only degree atomics ---------------
        __shared__ int s_is64;
        if (tid == 0) s_is64 = detect_is64(eidx);
        __syncthreads();
        const bool is64 = (s_is64 != 0);

        const int tiles = (E + 2047) / 2048;
        for (int tile = blockIdx.x; tile < tiles; tile += EDGE_ROLE_BLOCKS) {
            const int base = tile * 2048 + tid * 8;
            if (base >= E) continue;

            if (base + 7 < E) {
                int c[8];
                if (is64) {
                    const long long* C = reinterpret_cast<const long long*>(eidx) + E;
                    longlong2 c01 = __ldcs(reinterpret_cast<const longlong2*>(C + base));
                    longlong2 c23 = __ldcs(reinterpret_cast<const longlong2*>(C + base + 2));
                    longlong2 c45 = __ldcs(reinterpret_cast<const longlong2*>(C + base + 4));
                    longlong2 c67 = __ldcs(reinterpret_cast<const longlong2*>(C + base + 6));
                    c[0]=(int)c01.x; c[1]=(int)c01.y; c[2]=(int)c23.x; c[3]=(int)c23.y;
                    c[4]=(int)c45.x; c[5]=(int)c45.y; c[6]=(int)c67.x; c[7]=(int)c67.y;
                } else {
                    const int* C = reinterpret_cast<const int*>(eidx) + E;
                    int4 a = __ldcs(reinterpret_cast<const int4*>(C + base));
                    int4 d = __ldcs(reinterpret_cast<const int4*>(C + base + 4));
                    c[0]=a.x; c[1]=a.y; c[2]=a.z; c[3]=a.w;
                    c[4]=d.x; c[5]=d.y; c[6]=d.z; c[7]=d.w;
                }
                #pragma unroll
                for (int k = 0; k < 8; k++) atomicAdd(&g_deg[c[k]], 1.0f);
            } else {
                for (int e = base; e < E; e++) {
                    int cc = is64
                        ? (int)reinterpret_cast<const long long*>(eidx)[(size_t)E + e]
                        : reinterpret_cast<const int*>(eidx)[(size_t)E + e];
                    atomicAdd(&g_deg[cc], 1.0f);
                }
            }
        }
    } else {
        // ---------------- diag role: 16 rows per block, 2 rows per warp ----
        const int db   = blockIdx.x - EDGE_ROLE_BLOCKS;
        const int lane = tid & 31;
        const int wrp  = tid >> 5;
        const int row0 = db * 16 + wrp * 2;
        if (row0 >= n) return;
        const int row1 = row0 + 1;
        const bool has1 = (row1 < n);

        const float4* x4 = reinterpret_cast<const float4*>(x);
        const float4* w4 = reinterpret_cast<const float4*>(w);

        float4 a0 = __ldcs(&x4[(size_t)row0 * 64 + lane]);
        float4 a1 = __ldcs(&x4[(size_t)row0 * 64 + lane + 32]);
        float4 c0 = make_float4(0.f, 0.f, 0.f, 0.f);
        float4 c1 = make_float4(0.f, 0.f, 0.f, 0.f);
        if (has1) {
            c0 = __ldcs(&x4[(size_t)row1 * 64 + lane]);
            c1 = __ldcs(&x4[(size_t)row1 * 64 + lane + 32]);
        }
        float4 w0 = __ldg(&w4[lane]);
        float4 w1 = __ldg(&w4[lane + 32]);

        float s0 = a0.x*w0.x + a0.y*w0.y + a0.z*w0.z + a0.w*w0.w
                 + a1.x*w1.x + a1.y*w1.y + a1.z*w1.z + a1.w*w1.w;
        float s1 = c0.x*w0.x + c0.y*w0.y + c0.z*w0.z + c0.w*w0.w
                 + c1.x*w1.x + c1.y*w1.y + c1.z*w1.z + c1.w*w1.w;

        #pragma unroll
        for (int o = 16; o; o >>= 1) {
            s0 += __shfl_xor_sync(0xFFFFFFFFu, s0, o);
            s1 += __shfl_xor_sync(0xFFFFFFFFu, s1, o);
        }

        if (lane == 0) {
            float bb = __ldg(b);
            g_diag[row0] = 1.0f / (1.0f + expf(-(s0 + bb)));
            if (has1) g_diag[row1] = 1.0f / (1.0f + expf(-(s1 + bb)));
        }
    }
}

// ---------------------------------------------------------------------------
// val: single pass over edges. Reads int64/int32 indices directly, computes
// vals[e] = (1/deg[row]) * attr[e] * diag[col]; mode3 also writes float
// row/col. 8 edges/thread; streaming hints keep L1 for the gather tables.
// ---------------------------------------------------------------------------
__global__ void val_kernel(const void* __restrict__ eidx,
                           const float* __restrict__ attr,
                           float* __restrict__ out,
                           int E, int mode3) {
    __shared__ int s_is64;
    if (threadIdx.x == 0) s_is64 = detect_is64(eidx);
    __syncthreads();
    bool is64 = (s_is64 != 0);

    int base = (blockIdx.x * blockDim.x + threadIdx.x) * 8;
    if (base >= E) return;
    float* vo = mode3 ? (out + (size_t)2 * E) : out;

    if (base + 7 < E) {
        int r[8], c[8];
        if (is64) {
            const long long* R = reinterpret_cast<const long long*>(eidx);
            const long long* C = R + E;
            longlong2 r01 = __ldcs(reinterpret_cast<const longlong2*>(R + base));
            longlong2 r23 = __ldcs(reinterpret_cast<const longlong2*>(R + base + 2));
            longlong2 r45 = __ldcs(reinterpret_cast<const longlong2*>(R + base + 4));
            longlong2 r67 = __ldcs(reinterpret_cast<const longlong2*>(R + base + 6));
            longlong2 c01 = __ldcs(reinterpret_cast<const longlong2*>(C + base));
            longlong2 c23 = __ldcs(reinterpret_cast<const longlong2*>(C + base + 2));
            longlong2 c45 = __ldcs(reinterpret_cast<const longlong2*>(C + base + 4));
            longlong2 c67 = __ldcs(reinterpret_cast<const longlong2*>(C + base + 6));
            r[0]=(int)r01.x; r[1]=(int)r01.y; r[2]=(int)r23.x; r[3]=(int)r23.y;
            r[4]=(int)r45.x; r[5]=(int)r45.y; r[6]=(int)r67.x; r[7]=(int)r67.y;
            c[0]=(int)c01.x; c[1]=(int)c01.y; c[2]=(int)c23.x; c[3]=(int)c23.y;
            c[4]=(int)c45.x; c[5]=(int)c45.y; c[6]=(int)c67.x; c[7]=(int)c67.y;
        } else {
            const int* R = reinterpret_cast<const int*>(eidx);
            const int* C = R + E;
            int4 ra = __ldcs(reinterpret_cast<const int4*>(R + base));
            int4 rb = __ldcs(reinterpret_cast<const int4*>(R + base + 4));
            int4 ca = __ldcs(reinterpret_cast<const int4*>(C + base));
            int4 cb = __ldcs(reinterpret_cast<const int4*>(C + base + 4));
            r[0]=ra.x; r[1]=ra.y; r[2]=ra.z; r[3]=ra.w;
            r[4]=rb.x; r[5]=rb.y; r[6]=rb.z; r[7]=rb.w;
            c[0]=ca.x; c[1]=ca.y; c[2]=ca.z; c[3]=ca.w;
            c[4]=cb.x; c[5]=cb.y; c[6]=cb.z; c[7]=cb.w;
        }

        const float4* AF = reinterpret_cast<const float4*>(attr + base);
        float4 a0 = __ldcs(AF), a1 = __ldcs(AF + 1);
        float a[8] = {a0.x, a0.y, a0.z, a0.w, a1.x, a1.y, a1.z, a1.w};

        float dr[8], dg[8];
        #pragma unroll
        for (int k = 0; k < 8; k++) dr[k] = __ldg(&g_deg[r[k]]);
        #pragma unroll
        for (int k = 0; k < 8; k++) dg[k] = __ldg(&g_diag[c[k]]);

        float v[8];
        #pragma unroll
        for (int k = 0; k < 8; k++) v[k] = (1.0f / dr[k]) * a[k] * dg[k];

        if (mode3) {
            __stcs(reinterpret_cast<float4*>(out + base),
                   make_float4((float)r[0], (float)r[1], (float)r[2], (float)r[3]));
            __stcs(reinterpret_cast<float4*>(out + base + 4),
                   make_float4((float)r[4], (float)r[5], (float)r[6], (float)r[7]));
            __stcs(reinterpret_cast<float4*>(out + (size_t)E + base),
                   make_float4((float)c[0], (float)c[1], (float)c[2], (float)c[3]));
            __stcs(reinterpret_cast<float4*>(out + (size_t)E + base + 4),
                   make_float4((float)c[4], (float)c[5], (float)c[6], (float)c[7]));
        }
        __stcs(reinterpret_cast<float4*>(vo + base),
               make_float4(v[0], v[1], v[2], v[3]));
        __stcs(reinterpret_cast<float4*>(vo + base + 4),
               make_float4(v[4], v[5], v[6], v[7]));
    } else {
        for (int e = base; e < E; e++) {
            int rr, cc;
            if (is64) {
                rr = (int)reinterpret_cast<const long long*>(eidx)[e];
                cc = (int)reinterpret_cast<const long long*>(eidx)[(size_t)E + e];
            } else {
                rr = reinterpret_cast<const int*>(eidx)[e];
                cc = reinterpret_cast<const int*>(eidx)[(size_t)E + e];
            }
            if (mode3) { out[e] = (float)rr; out[(size_t)E + e] = (float)cc; }
            vo[e] = (1.0f / __ldg(&g_deg[rr])) * attr[e] * __ldg(&g_diag[cc]);
        }
    }
}

// ---------------------------------------------------------------------------
// Launch: memset -> combined (diag || col-only deg) -> val. 3 graph nodes.
// ---------------------------------------------------------------------------
extern "C" void kernel_launch(void* const* d_in, const int* in_sizes, int n_in,
                              void* d_out, int out_size) {
    const float* x    = (const float*)d_in[0];
    const void*  ei   = d_in[1];
    const float* attr = (const float*)d_in[2];
    const float* w    = (const float*)d_in[3];
    const float* b    = (const float*)d_in[4];
    float* out = (float*)d_out;

    int E = in_sizes[2];
    int N = in_sizes[0] / FEAT_D;
    int mode3 = (out_size >= 3 * E) ? 1 : 0;

    static void* deg_addr = nullptr;
    if (deg_addr == nullptr) cudaGetSymbolAddress(&deg_addr, g_deg);

    // zero degree counts
    cudaMemsetAsync(deg_addr, 0, (size_t)N * sizeof(float), 0);

    // combined: 444 persistent edge blocks + one-shot diag blocks
    int diag_blocks = (N + 15) / 16;                 // 6250
    int grid = EDGE_ROLE_BLOCKS + diag_blocks;
    fused_deg_diag<<<grid, 256>>>(x, w, b, ei, N, E);

    // single-pass values (+ index conversion)
    int vthreads = (E + 7) / 8;
    int vblocks  = (vthreads + 255) / 256;
    val_kernel<<<vblocks, 256>>>(ei, attr, out, E, mode3);
}